// round 1
// baseline (speedup 1.0000x reference)
#include <cuda_runtime.h>
#include <math.h>

// Problem constants (match reference setup_inputs)
#define NN    50000
#define EEDG  500000
#define CIN   128
#define HIDC  64
#define NHEAD 4
#define C2    256   // NHEAD * HIDC

// ---------------- scratch (static __device__ — no allocation allowed) ----------------
__device__ float g_XL [NN * C2];          // 51.2 MB
__device__ float g_XR [NN * C2];          // 51.2 MB
__device__ float g_EE [(size_t)EEDG * C2];// 512 MB
__device__ float g_H0 [NN * HIDC];
__device__ float g_H1 [NN * HIDC];
__device__ float g_RES[NN * HIDC];
__device__ int   g_off[NN + 1];
__device__ int   g_cur[NN];
__device__ int   g_eid[EEDG];
__device__ int   g_cnt[NN];
__device__ int   g_bsum[64];

// ---------------- CSR build ----------------
__global__ void hist_kernel(const int* __restrict__ dst, int E, int* __restrict__ cnt) {
    int e = blockIdx.x * blockDim.x + threadIdx.x;
    if (e < E) atomicAdd(&cnt[dst[e]], 1);
}

__global__ void scan_block(const int* __restrict__ cnt, int N,
                           int* __restrict__ off, int* __restrict__ bsum) {
    __shared__ int s[1024];
    int i = blockIdx.x * 1024 + threadIdx.x;
    int v = (i < N) ? cnt[i] : 0;
    s[threadIdx.x] = v;
    __syncthreads();
    #pragma unroll
    for (int d = 1; d < 1024; d <<= 1) {
        int t = (threadIdx.x >= d) ? s[threadIdx.x - d] : 0;
        __syncthreads();
        if (threadIdx.x >= d) s[threadIdx.x] += t;
        __syncthreads();
    }
    if (i < N) off[i] = s[threadIdx.x] - v;    // exclusive within block
    if (threadIdx.x == 1023) bsum[blockIdx.x] = s[1023];
}

__global__ void scan_small(int* bsum, int nb) {
    if (threadIdx.x == 0 && blockIdx.x == 0) {
        int acc = 0;
        for (int i = 0; i < nb; i++) { int v = bsum[i]; bsum[i] = acc; acc += v; }
    }
}

__global__ void finalize_offsets(int N, int E, const int* __restrict__ bsum,
                                 int* __restrict__ off, int* __restrict__ cur) {
    int i = blockIdx.x * blockDim.x + threadIdx.x;
    if (i < N) {
        int v = off[i] + bsum[i >> 10];
        off[i] = v;
        cur[i] = v;
    }
    if (i == 0) off[N] = E;
}

__global__ void scatter_kernel(const int* __restrict__ dst, int E,
                               int* __restrict__ cur, int* __restrict__ eid) {
    int e = blockIdx.x * blockDim.x + threadIdx.x;
    if (e < E) {
        int d = dst[e];
        int p = atomicAdd(&cur[d], 1);
        eid[p] = e;
    }
}

// ---------------- SGEMM: C[M,Ncols] = A[M,K] @ B[K,Ncols] (+bias), row-major ----------------
// 128x128 tile, BK=16, 256 threads, 8x8 per thread.
__global__ void sgemm_bias(int M, int K, int Ncols,
                           const float* __restrict__ A, const float* __restrict__ B,
                           const float* __restrict__ bias, float* __restrict__ C) {
    __shared__ float As[16][132];
    __shared__ float Bs[16][132];
    const int tid = threadIdx.x;
    const int tx = tid & 15, ty = tid >> 4;
    const int row0 = blockIdx.y * 128, col0 = blockIdx.x * 128;

    float acc[8][8];
    #pragma unroll
    for (int i = 0; i < 8; i++)
        #pragma unroll
        for (int j = 0; j < 8; j++) acc[i][j] = 0.f;

    for (int k0 = 0; k0 < K; k0 += 16) {
        // load A tile (128 rows x 16 k) = 512 float4 slots
        #pragma unroll
        for (int q = 0; q < 2; q++) {
            int s  = tid + q * 256;
            int r  = s >> 2;
            int kk = (s & 3) << 2;
            float4 a = make_float4(0.f, 0.f, 0.f, 0.f);
            if (row0 + r < M)
                a = *(const float4*)(A + (size_t)(row0 + r) * K + k0 + kk);
            As[kk + 0][r] = a.x; As[kk + 1][r] = a.y;
            As[kk + 2][r] = a.z; As[kk + 3][r] = a.w;
        }
        // load B tile (16 k x 128 cols) = 512 float4 slots
        #pragma unroll
        for (int q = 0; q < 2; q++) {
            int s  = tid + q * 256;
            int kk = s >> 5;
            int c  = (s & 31) << 2;
            float4 b = make_float4(0.f, 0.f, 0.f, 0.f);
            if (col0 + c < Ncols)
                b = *(const float4*)(B + (size_t)(k0 + kk) * Ncols + col0 + c);
            Bs[kk][c + 0] = b.x; Bs[kk][c + 1] = b.y;
            Bs[kk][c + 2] = b.z; Bs[kk][c + 3] = b.w;
        }
        __syncthreads();
        #pragma unroll
        for (int kk = 0; kk < 16; kk++) {
            float4 a0 = *(const float4*)&As[kk][ty * 8];
            float4 a1 = *(const float4*)&As[kk][ty * 8 + 4];
            float4 b0 = *(const float4*)&Bs[kk][tx * 8];
            float4 b1 = *(const float4*)&Bs[kk][tx * 8 + 4];
            float av[8] = {a0.x, a0.y, a0.z, a0.w, a1.x, a1.y, a1.z, a1.w};
            float bv[8] = {b0.x, b0.y, b0.z, b0.w, b1.x, b1.y, b1.z, b1.w};
            #pragma unroll
            for (int i = 0; i < 8; i++)
                #pragma unroll
                for (int j = 0; j < 8; j++) acc[i][j] = fmaf(av[i], bv[j], acc[i][j]);
        }
        __syncthreads();
    }

    #pragma unroll
    for (int i = 0; i < 8; i++) {
        int r = row0 + ty * 8 + i;
        if (r >= M) continue;
        #pragma unroll
        for (int jq = 0; jq < 2; jq++) {
            int c = col0 + tx * 8 + jq * 4;
            if (c < Ncols) {
                float4 v;
                v.x = acc[i][jq * 4 + 0] + (bias ? bias[c + 0] : 0.f);
                v.y = acc[i][jq * 4 + 1] + (bias ? bias[c + 1] : 0.f);
                v.z = acc[i][jq * 4 + 2] + (bias ? bias[c + 2] : 0.f);
                v.w = acc[i][jq * 4 + 3] + (bias ? bias[c + 3] : 0.f);
                *(float4*)(C + (size_t)r * Ncols + c) = v;
            }
        }
    }
}

// ---------------- fused GATv2 aggregation: one warp per destination node ----------------
// lane holds 8 contiguous channels [8*lane, 8*lane+8); head = lane>>3 (64 ch per head).
// Online softmax over incoming edges; mean over heads; bias; optional BN+residual+ReLU.
__global__ void gat_aggregate(int n_nodes,
                              const float* __restrict__ XL, const float* __restrict__ XR,
                              const float* __restrict__ EEp,
                              const int* __restrict__ off, const int* __restrict__ eid,
                              const int* __restrict__ src,
                              const float* __restrict__ att, const float* __restrict__ bias,
                              const float* __restrict__ bng, const float* __restrict__ bnb,
                              const float* __restrict__ bnrm, const float* __restrict__ bnrv,
                              const float* __restrict__ residual,
                              float* __restrict__ outp, int bnrelu) {
    int gw   = (blockIdx.x * blockDim.x + threadIdx.x) >> 5;
    int lane = threadIdx.x & 31;
    if (gw >= n_nodes) return;
    const int n = gw;
    const int base = lane * 8;

    float xr[8], atv[8];
    {
        float4 t0 = *(const float4*)(XR + (size_t)n * C2 + base);
        float4 t1 = *(const float4*)(XR + (size_t)n * C2 + base + 4);
        xr[0]=t0.x; xr[1]=t0.y; xr[2]=t0.z; xr[3]=t0.w;
        xr[4]=t1.x; xr[5]=t1.y; xr[6]=t1.z; xr[7]=t1.w;
        float4 u0 = *(const float4*)(att + base);
        float4 u1 = *(const float4*)(att + base + 4);
        atv[0]=u0.x; atv[1]=u0.y; atv[2]=u0.z; atv[3]=u0.w;
        atv[4]=u1.x; atv[5]=u1.y; atv[6]=u1.z; atv[7]=u1.w;
    }

    float m = -1e30f, dsum = 0.f;
    float acc[8];
    #pragma unroll
    for (int j = 0; j < 8; j++) acc[j] = 0.f;

    const int i0 = off[n], i1 = off[n + 1];
    for (int idx = i0; idx < i1; ++idx) {
        int e = eid[idx];
        int s = src[e];
        float el[8];
        {
            float4 t0 = *(const float4*)(XL + (size_t)s * C2 + base);
            float4 t1 = *(const float4*)(XL + (size_t)s * C2 + base + 4);
            el[0]=t0.x; el[1]=t0.y; el[2]=t0.z; el[3]=t0.w;
            el[4]=t1.x; el[5]=t1.y; el[6]=t1.z; el[7]=t1.w;
        }
        float p = 0.f;
        {
            const float* eer = EEp + (size_t)e * C2 + base;
            float4 t0 = *(const float4*)eer;
            float4 t1 = *(const float4*)(eer + 4);
            float ev[8] = {t0.x, t0.y, t0.z, t0.w, t1.x, t1.y, t1.z, t1.w};
            #pragma unroll
            for (int j = 0; j < 8; j++) {
                float z = el[j] + xr[j] + ev[j];
                z = (z > 0.f) ? z : 0.2f * z;          // leaky_relu(0.2)
                p = fmaf(z, atv[j], p);
            }
        }
        // per-head logit: reduce within the 8-lane group of this head
        p += __shfl_xor_sync(0xffffffffu, p, 1);
        p += __shfl_xor_sync(0xffffffffu, p, 2);
        p += __shfl_xor_sync(0xffffffffu, p, 4);
        // online softmax update
        float nm = fmaxf(m, p);
        float sc = __expf(m - nm);
        float f  = __expf(p - nm);
        dsum = dsum * sc + f;
        #pragma unroll
        for (int j = 0; j < 8; j++) acc[j] = fmaf(acc[j], sc, f * el[j]);
        m = nm;
    }

    float inv = (i1 > i0) ? (1.0f / dsum) : 0.f;
    float v[8];
    #pragma unroll
    for (int j = 0; j < 8; j++) {
        float t = acc[j] * inv;
        // mean over heads: lanes l, l+8, l+16, l+24 hold the same channel
        t += __shfl_xor_sync(0xffffffffu, t, 8);
        t += __shfl_xor_sync(0xffffffffu, t, 16);
        v[j] = t * 0.25f;
    }

    if (lane < 8) {
        int c0 = lane * 8;
        #pragma unroll
        for (int j = 0; j < 8; j++) {
            int c = c0 + j;
            float t = v[j] + bias[c];
            if (bnrelu) {
                t = (t - bnrm[c]) * rsqrtf(bnrv[c] + 1e-5f) * bng[c] + bnb[c];
                t += residual[(size_t)n * HIDC + c];
                t = fmaxf(t, 0.f);
            }
            outp[(size_t)n * HIDC + c] = t;
        }
    }
}

// ---------------- passthrough copy (edge_attr -> second output) ----------------
__global__ void copy_f4(const float4* __restrict__ s, float4* __restrict__ d, int n4) {
    int i = blockIdx.x * blockDim.x + threadIdx.x;
    int stride = gridDim.x * blockDim.x;
    for (; i < n4; i += stride) d[i] = s[i];
}

static inline int cdiv(int a, int b) { return (a + b - 1) / b; }

extern "C" void kernel_launch(void* const* d_in, const int* in_sizes, int n_in,
                              void* d_out, int out_size) {
    const float* x      = (const float*)d_in[0];
    const int*   ei     = (const int*)  d_in[1];
    const float* ea     = (const float*)d_in[2];
    const float* res_W  = (const float*)d_in[3];
    const float* res_b  = (const float*)d_in[4];
    const float* Wl0    = (const float*)d_in[5];
    const float* bl0    = (const float*)d_in[6];
    const float* Wr0    = (const float*)d_in[7];
    const float* br0    = (const float*)d_in[8];
    const float* We0    = (const float*)d_in[9];
    const float* att0   = (const float*)d_in[10];
    const float* bias0  = (const float*)d_in[11];
    const float* Wl12   = (const float*)d_in[12];
    const float* bl12   = (const float*)d_in[13];
    const float* Wr12   = (const float*)d_in[14];
    const float* br12   = (const float*)d_in[15];
    const float* We12   = (const float*)d_in[16];
    const float* att12  = (const float*)d_in[17];
    const float* bias12 = (const float*)d_in[18];
    const float* bng    = (const float*)d_in[19];
    const float* bnb    = (const float*)d_in[20];
    const float* bnrm   = (const float*)d_in[21];
    const float* bnrv   = (const float*)d_in[22];

    const int N = in_sizes[0] / CIN;
    const int E = in_sizes[1] / 2;
    const int* srcp = ei;
    const int* dstp = ei + E;
    float* out = (float*)d_out;

    float *XL, *XR, *EEb, *H0, *H1, *RES;
    int *off, *cur, *eid, *cnt, *bsum;
    cudaGetSymbolAddress((void**)&XL,  g_XL);
    cudaGetSymbolAddress((void**)&XR,  g_XR);
    cudaGetSymbolAddress((void**)&EEb, g_EE);
    cudaGetSymbolAddress((void**)&H0,  g_H0);
    cudaGetSymbolAddress((void**)&H1,  g_H1);
    cudaGetSymbolAddress((void**)&RES, g_RES);
    cudaGetSymbolAddress((void**)&off, g_off);
    cudaGetSymbolAddress((void**)&cur, g_cur);
    cudaGetSymbolAddress((void**)&eid, g_eid);
    cudaGetSymbolAddress((void**)&cnt, g_cnt);
    cudaGetSymbolAddress((void**)&bsum,g_bsum);

    // ---- CSR by destination ----
    cudaMemsetAsync(cnt, 0, sizeof(int) * N);
    hist_kernel<<<cdiv(E, 256), 256>>>(dstp, E, cnt);
    int nb = cdiv(N, 1024);
    scan_block<<<nb, 1024>>>(cnt, N, off, bsum);
    scan_small<<<1, 32>>>(bsum, nb);
    finalize_offsets<<<cdiv(N, 256), 256>>>(N, E, bsum, off, cur);
    scatter_kernel<<<cdiv(E, 256), 256>>>(dstp, E, cur, eid);

    // ---- residual projection ----
    sgemm_bias<<<dim3(1, cdiv(N, 128)), 256>>>(N, CIN, HIDC, x, res_W, res_b, RES);

    dim3 gN(2, cdiv(N, 128));
    dim3 gE(2, cdiv(E, 128));
    int aggGrid = cdiv(N * 32, 256);

    // ---- layer 0 (in=128, BN + residual-projection + ReLU) ----
    sgemm_bias<<<gN, 256>>>(N, CIN, C2, x, Wl0, bl0, XL);
    sgemm_bias<<<gN, 256>>>(N, CIN, C2, x, Wr0, br0, XR);
    sgemm_bias<<<gE, 256>>>(E, CIN, C2, ea, We0, nullptr, EEb);
    gat_aggregate<<<aggGrid, 256>>>(N, XL, XR, EEb, off, eid, srcp,
                                    att0, bias0, bng, bnb, bnrm, bnrv, RES, H0, 1);

    // ---- layer 1 (in=64, BN + identity residual + ReLU) ----
    sgemm_bias<<<gN, 256>>>(N, HIDC, C2, H0, Wl12, bl12, XL);
    sgemm_bias<<<gN, 256>>>(N, HIDC, C2, H0, Wr12, br12, XR);
    sgemm_bias<<<gE, 256>>>(E, CIN, C2, ea, We12, nullptr, EEb);
    gat_aggregate<<<aggGrid, 256>>>(N, XL, XR, EEb, off, eid, srcp,
                                    att12, bias12, bng + HIDC, bnb + HIDC,
                                    bnrm + HIDC, bnrv + HIDC, H0, H1, 1);

    // ---- layer 2 (final conv, no BN/ReLU) ----
    sgemm_bias<<<gN, 256>>>(N, HIDC, C2, H1, Wl12 + HIDC * C2, bl12 + C2, XL);
    sgemm_bias<<<gN, 256>>>(N, HIDC, C2, H1, Wr12 + HIDC * C2, br12 + C2, XR);
    sgemm_bias<<<gE, 256>>>(E, CIN, C2, ea, We12 + CIN * C2, nullptr, EEb);
    gat_aggregate<<<aggGrid, 256>>>(N, XL, XR, EEb, off, eid, srcp,
                                    att12 + C2, bias12 + HIDC,
                                    nullptr, nullptr, nullptr, nullptr, nullptr, out, 0);

    // ---- second output: edge_attr passthrough ----
    copy_f4<<<4096, 256>>>((const float4*)ea, (float4*)(out + (size_t)N * HIDC),
                           E * CIN / 4);
}

// round 7
// speedup vs baseline: 1.2418x; 1.2418x over previous
#include <cuda_runtime.h>
#include <cuda_bf16.h>
#include <math.h>
#include <stdint.h>

// Problem constants (match reference setup_inputs)
#define NN    50000
#define EEDG  500000
#define CIN   128
#define HIDC  64
#define NHEAD 4
#define C2    256   // NHEAD * HIDC

// =================== scratch (static __device__) ===================
__device__ float g_XL [NN * C2];
__device__ float g_XR [NN * C2];
__device__ float g_EE [(size_t)EEDG * C2];
__device__ float g_H0 [NN * HIDC];
__device__ float g_H1 [NN * HIDC];
__device__ float g_RES[NN * HIDC];
__device__ int   g_off[NN + 1];
__device__ int   g_cur[NN];
__device__ int   g_eid[EEDG];
__device__ int   g_cnt[NN];
__device__ int   g_bsum[64];
__device__ __align__(16) char g_Bimg[950272];   // bf16 hi/lo weight images (plain row-major)

// =================== PTX helpers (compute_103-legal only) ===================
__device__ __forceinline__ uint32_t smem_to_u32(const void* p) {
    uint32_t a;
    asm("{ .reg .u64 t; cvta.to.shared.u64 t, %1; cvt.u32.u64 %0, t; }" : "=r"(a) : "l"(p));
    return a;
}
__device__ __forceinline__ void ldsm4(uint32_t* r, uint32_t a) {
    asm volatile("ldmatrix.sync.aligned.m8n8.x4.shared.b16 {%0,%1,%2,%3}, [%4];"
        : "=r"(r[0]), "=r"(r[1]), "=r"(r[2]), "=r"(r[3]) : "r"(a));
}
__device__ __forceinline__ void ldsm4t(uint32_t* r, uint32_t a) {
    asm volatile("ldmatrix.sync.aligned.m8n8.x4.trans.shared.b16 {%0,%1,%2,%3}, [%4];"
        : "=r"(r[0]), "=r"(r[1]), "=r"(r[2]), "=r"(r[3]) : "r"(a));
}
__device__ __forceinline__ void mma16816(float* c, const uint32_t* a, const uint32_t* b) {
    asm volatile(
        "mma.sync.aligned.m16n8k16.row.col.f32.bf16.bf16.f32 "
        "{%0,%1,%2,%3}, {%4,%5,%6,%7}, {%8,%9}, {%0,%1,%2,%3};"
        : "+f"(c[0]), "+f"(c[1]), "+f"(c[2]), "+f"(c[3])
        : "r"(a[0]), "r"(a[1]), "r"(a[2]), "r"(a[3]), "r"(b[0]), "r"(b[1]));
}

// =================== CSR build ===================
__global__ void hist_kernel(const int* __restrict__ dst, int E, int* __restrict__ cnt) {
    int e = blockIdx.x * blockDim.x + threadIdx.x;
    if (e < E) atomicAdd(&cnt[dst[e]], 1);
}
__global__ void scan_block(const int* __restrict__ cnt, int N,
                           int* __restrict__ off, int* __restrict__ bsum) {
    __shared__ int s[1024];
    int i = blockIdx.x * 1024 + threadIdx.x;
    int v = (i < N) ? cnt[i] : 0;
    s[threadIdx.x] = v;
    __syncthreads();
    #pragma unroll
    for (int d = 1; d < 1024; d <<= 1) {
        int t = (threadIdx.x >= d) ? s[threadIdx.x - d] : 0;
        __syncthreads();
        if (threadIdx.x >= d) s[threadIdx.x] += t;
        __syncthreads();
    }
    if (i < N) off[i] = s[threadIdx.x] - v;
    if (threadIdx.x == 1023) bsum[blockIdx.x] = s[1023];
}
__global__ void scan_small(int* bsum, int nb) {
    if (threadIdx.x == 0 && blockIdx.x == 0) {
        int acc = 0;
        for (int i = 0; i < nb; i++) { int v = bsum[i]; bsum[i] = acc; acc += v; }
    }
}
__global__ void finalize_offsets(int N, int E, const int* __restrict__ bsum,
                                 int* __restrict__ off, int* __restrict__ cur) {
    int i = blockIdx.x * blockDim.x + threadIdx.x;
    if (i < N) { int v = off[i] + bsum[i >> 10]; off[i] = v; cur[i] = v; }
    if (i == 0) off[N] = E;
}
__global__ void scatter_kernel(const int* __restrict__ dst, int E,
                               int* __restrict__ cur, int* __restrict__ eid) {
    int e = blockIdx.x * blockDim.x + threadIdx.x;
    if (e < E) { int p = atomicAdd(&cur[dst[e]], 1); eid[p] = e; }
}

// =================== weight prep: W[K,N] fp32 -> bf16 hi (img[0:K*N]) + lo (img[K*N:]) ===================
__global__ void prep_B(const float* __restrict__ W, int K, int N, __nv_bfloat16* __restrict__ img) {
    int i = blockIdx.x * blockDim.x + threadIdx.x;
    if (i >= K * N) return;
    float a = W[i];
    __nv_bfloat16 h = __float2bfloat16(a);
    __nv_bfloat16 l = __float2bfloat16(a - __bfloat162float(h));
    img[i] = h;
    img[K * N + i] = l;
}

// =================== tensor-core GEMM via mma.sync (bf16 hi/lo 3-pass) ===================
// C[M,N] = A[M,K] @ W[K,N] (+bias). CTA = 128 rows x 128 cols (grid.y picks 128-col chunk).
// 256 threads = 8 warps as 2(M) x 4(N); warp tile 64x32 = 4x4 m16n8k16 tiles.
__global__ __launch_bounds__(256) void tc_gemm(
    int M, int K, int N,
    const float* __restrict__ A, const __nv_bfloat16* __restrict__ Bimg,
    const float* __restrict__ bias, float* __restrict__ C)
{
    extern __shared__ char smem[];
    const int tid  = threadIdx.x;
    const int wid  = tid >> 5, lane = tid & 31;
    const int m0   = blockIdx.x * 128;
    const int n0   = blockIdx.y * 128;

    const int PA = K + 8;     // bf16 elements per A smem row
    const int PB = 136;       // 128 + 8
    const uint32_t A_sz = (uint32_t)128 * PA * 2;   // bytes (one term)
    const uint32_t B_sz = (uint32_t)K * PB * 2;
    char* Ah = smem;
    char* Al = smem + A_sz;
    char* Bh = smem + 2 * A_sz;
    char* Bl = smem + 2 * A_sz + B_sz;

    // ---- A tile: fp32 -> bf16 hi/lo ----
    {
        const int rf4 = K >> 2;                 // float4 per row
        for (int idx = tid; idx < 128 * rf4; idx += 256) {
            int row = idx / rf4, col = (idx - row * rf4) * 4;
            int gr = m0 + row;
            float4 v = make_float4(0.f, 0.f, 0.f, 0.f);
            if (gr < M) v = *(const float4*)(A + (size_t)gr * K + col);
            float f[4] = {v.x, v.y, v.z, v.w};
            uint32_t hp[2], lp[2];
            #pragma unroll
            for (int q = 0; q < 2; q++) {
                float a0 = f[2 * q], a1 = f[2 * q + 1];
                __nv_bfloat16 h0 = __float2bfloat16(a0), h1 = __float2bfloat16(a1);
                __nv_bfloat16 l0 = __float2bfloat16(a0 - __bfloat162float(h0));
                __nv_bfloat16 l1 = __float2bfloat16(a1 - __bfloat162float(h1));
                hp[q] = ((uint32_t)__bfloat16_as_ushort(h1) << 16) | __bfloat16_as_ushort(h0);
                lp[q] = ((uint32_t)__bfloat16_as_ushort(l1) << 16) | __bfloat16_as_ushort(l0);
            }
            uint32_t boff = ((uint32_t)row * PA + col) * 2;
            *(uint32_t*)(Ah + boff)     = hp[0];
            *(uint32_t*)(Ah + boff + 4) = hp[1];
            *(uint32_t*)(Al + boff)     = lp[0];
            *(uint32_t*)(Al + boff + 4) = lp[1];
        }
    }
    // ---- B tile: copy hi/lo bf16 images (zero-pad cols >= N) ----
    {
        const __nv_bfloat16* gh = Bimg;
        const __nv_bfloat16* gl = Bimg + (size_t)K * N;
        for (int idx = tid; idx < K * 16; idx += 256) {
            int row = idx >> 4, col = (idx & 15) * 8;
            uint4 vh = make_uint4(0, 0, 0, 0), vl = vh;
            if (n0 + col < N) {
                vh = *(const uint4*)(gh + (size_t)row * N + n0 + col);
                vl = *(const uint4*)(gl + (size_t)row * N + n0 + col);
            }
            uint32_t boff = ((uint32_t)row * PB + col) * 2;
            *(uint4*)(Bh + boff) = vh;
            *(uint4*)(Bl + boff) = vl;
        }
    }
    __syncthreads();

    // ---- mainloop ----
    const int wm = (wid >> 2) * 64;   // warp M offset in CTA tile
    const int wn = (wid & 3) * 32;    // warp N offset
    const int lr = lane & 15, lc = lane >> 4;

    float acc[4][4][4];
    #pragma unroll
    for (int i = 0; i < 4; i++)
        #pragma unroll
        for (int j = 0; j < 4; j++)
            #pragma unroll
            for (int q = 0; q < 4; q++) acc[i][j][q] = 0.f;

    const uint32_t su = smem_to_u32(smem);
    const uint32_t aAddr0 = su + (((uint32_t)(wm + lr) * PA + lc * 8) * 2);
    const uint32_t bAddr0 = su + 2 * A_sz + (((uint32_t)lr * PB + wn + lc * 8) * 2);
    const int ksteps = K >> 4;

    for (int ks = 0; ks < ksteps; ks++) {
        const uint32_t ka = aAddr0 + (uint32_t)ks * 32;           // 16 cols * 2B
        const uint32_t kb = bAddr0 + (uint32_t)ks * 16 * PB * 2;  // 16 rows
        uint32_t a[4][4], bh[4][2], bl[4][2];
        #pragma unroll
        for (int mi = 0; mi < 4; mi++) ldsm4(a[mi], ka + (uint32_t)mi * 16 * PA * 2);
        #pragma unroll
        for (int nj = 0; nj < 2; nj++) {
            uint32_t t[4];
            ldsm4t(t, kb + (uint32_t)nj * 32);                    // hi
            bh[2 * nj][0] = t[0]; bh[2 * nj][1] = t[1];
            bh[2 * nj + 1][0] = t[2]; bh[2 * nj + 1][1] = t[3];
            ldsm4t(t, kb + B_sz + (uint32_t)nj * 32);             // lo
            bl[2 * nj][0] = t[0]; bl[2 * nj][1] = t[1];
            bl[2 * nj + 1][0] = t[2]; bl[2 * nj + 1][1] = t[3];
        }
        #pragma unroll
        for (int mi = 0; mi < 4; mi++)
            #pragma unroll
            for (int ni = 0; ni < 4; ni++) mma16816(acc[mi][ni], a[mi], bh[ni]);
        #pragma unroll
        for (int mi = 0; mi < 4; mi++)
            #pragma unroll
            for (int ni = 0; ni < 4; ni++) mma16816(acc[mi][ni], a[mi], bl[ni]);
        #pragma unroll
        for (int mi = 0; mi < 4; mi++) ldsm4(a[mi], ka + A_sz + (uint32_t)mi * 16 * PA * 2);
        #pragma unroll
        for (int mi = 0; mi < 4; mi++)
            #pragma unroll
            for (int ni = 0; ni < 4; ni++) mma16816(acc[mi][ni], a[mi], bh[ni]);
    }

    // ---- epilogue: direct stores with bias ----
    #pragma unroll
    for (int mi = 0; mi < 4; mi++) {
        int row = m0 + wm + mi * 16 + (lane >> 2);
        #pragma unroll
        for (int ni = 0; ni < 4; ni++) {
            int col = n0 + wn + ni * 8 + (lane & 3) * 2;
            if (col < N) {
                float b0 = bias ? bias[col]     : 0.f;
                float b1 = bias ? bias[col + 1] : 0.f;
                if (row < M) {
                    float2 v = make_float2(acc[mi][ni][0] + b0, acc[mi][ni][1] + b1);
                    *(float2*)(C + (size_t)row * N + col) = v;
                }
                if (row + 8 < M) {
                    float2 v = make_float2(acc[mi][ni][2] + b0, acc[mi][ni][3] + b1);
                    *(float2*)(C + (size_t)(row + 8) * N + col) = v;
                }
            }
        }
    }
}

// =================== fused GATv2 aggregation (one warp per destination node) ===================
__global__ void gat_aggregate(int n_nodes,
                              const float* __restrict__ XL, const float* __restrict__ XR,
                              const float* __restrict__ EEp,
                              const int* __restrict__ off, const int* __restrict__ eid,
                              const int* __restrict__ src,
                              const float* __restrict__ att, const float* __restrict__ bias,
                              const float* __restrict__ bng, const float* __restrict__ bnb,
                              const float* __restrict__ bnrm, const float* __restrict__ bnrv,
                              const float* __restrict__ residual,
                              float* __restrict__ outp, int bnrelu) {
    int gw   = (blockIdx.x * blockDim.x + threadIdx.x) >> 5;
    int lane = threadIdx.x & 31;
    if (gw >= n_nodes) return;
    const int n = gw;
    const int base = lane * 8;

    float xr[8], atv[8];
    {
        float4 t0 = *(const float4*)(XR + (size_t)n * C2 + base);
        float4 t1 = *(const float4*)(XR + (size_t)n * C2 + base + 4);
        xr[0]=t0.x; xr[1]=t0.y; xr[2]=t0.z; xr[3]=t0.w;
        xr[4]=t1.x; xr[5]=t1.y; xr[6]=t1.z; xr[7]=t1.w;
        float4 u0 = *(const float4*)(att + base);
        float4 u1 = *(const float4*)(att + base + 4);
        atv[0]=u0.x; atv[1]=u0.y; atv[2]=u0.z; atv[3]=u0.w;
        atv[4]=u1.x; atv[5]=u1.y; atv[6]=u1.z; atv[7]=u1.w;
    }

    float m = -1e30f, dsum = 0.f;
    float acc[8];
    #pragma unroll
    for (int j = 0; j < 8; j++) acc[j] = 0.f;

    const int i0 = off[n], i1 = off[n + 1];
    for (int idx = i0; idx < i1; ++idx) {
        int e = eid[idx];
        int s = src[e];
        float el[8];
        {
            float4 t0 = *(const float4*)(XL + (size_t)s * C2 + base);
            float4 t1 = *(const float4*)(XL + (size_t)s * C2 + base + 4);
            el[0]=t0.x; el[1]=t0.y; el[2]=t0.z; el[3]=t0.w;
            el[4]=t1.x; el[5]=t1.y; el[6]=t1.z; el[7]=t1.w;
        }
        float p = 0.f;
        {
            const float* eer = EEp + (size_t)e * C2 + base;
            float4 t0 = *(const float4*)eer;
            float4 t1 = *(const float4*)(eer + 4);
            float ev[8] = {t0.x, t0.y, t0.z, t0.w, t1.x, t1.y, t1.z, t1.w};
            #pragma unroll
            for (int j = 0; j < 8; j++) {
                float z = el[j] + xr[j] + ev[j];
                z = (z > 0.f) ? z : 0.2f * z;
                p = fmaf(z, atv[j], p);
            }
        }
        p += __shfl_xor_sync(0xffffffffu, p, 1);
        p += __shfl_xor_sync(0xffffffffu, p, 2);
        p += __shfl_xor_sync(0xffffffffu, p, 4);
        float nm = fmaxf(m, p);
        float sc = __expf(m - nm);
        float f  = __expf(p - nm);
        dsum = dsum * sc + f;
        #pragma unroll
        for (int j = 0; j < 8; j++) acc[j] = fmaf(acc[j], sc, f * el[j]);
        m = nm;
    }

    float inv = (i1 > i0) ? (1.0f / dsum) : 0.f;
    float v[8];
    #pragma unroll
    for (int j = 0; j < 8; j++) {
        float t = acc[j] * inv;
        t += __shfl_xor_sync(0xffffffffu, t, 8);
        t += __shfl_xor_sync(0xffffffffu, t, 16);
        v[j] = t * 0.25f;
    }

    if (lane < 8) {
        int c0 = lane * 8;
        #pragma unroll
        for (int j = 0; j < 8; j++) {
            int c = c0 + j;
            float t = v[j] + bias[c];
            if (bnrelu) {
                t = (t - bnrm[c]) * rsqrtf(bnrv[c] + 1e-5f) * bng[c] + bnb[c];
                t += residual[(size_t)n * HIDC + c];
                t = fmaxf(t, 0.f);
            }
            outp[(size_t)n * HIDC + c] = t;
        }
    }
}

__global__ void copy_f4(const float4* __restrict__ s, float4* __restrict__ d, int n4) {
    int i = blockIdx.x * blockDim.x + threadIdx.x;
    int stride = gridDim.x * blockDim.x;
    for (; i < n4; i += stride) d[i] = s[i];
}

static inline int cdiv(int a, int b) { return (a + b - 1) / b; }
static inline size_t img_bytes(int K, int N) { return (size_t)4 * K * N; }
static inline int smem_size(int K) {
    return 2 * (128 * (K + 8) * 2) + 2 * (K * 136 * 2);
}

extern "C" void kernel_launch(void* const* d_in, const int* in_sizes, int n_in,
                              void* d_out, int out_size) {
    const float* x      = (const float*)d_in[0];
    const int*   ei     = (const int*)  d_in[1];
    const float* ea     = (const float*)d_in[2];
    const float* res_W  = (const float*)d_in[3];
    const float* res_b  = (const float*)d_in[4];
    const float* Wl0    = (const float*)d_in[5];
    const float* bl0    = (const float*)d_in[6];
    const float* Wr0    = (const float*)d_in[7];
    const float* br0    = (const float*)d_in[8];
    const float* We0    = (const float*)d_in[9];
    const float* att0   = (const float*)d_in[10];
    const float* bias0  = (const float*)d_in[11];
    const float* Wl12   = (const float*)d_in[12];
    const float* bl12   = (const float*)d_in[13];
    const float* Wr12   = (const float*)d_in[14];
    const float* br12   = (const float*)d_in[15];
    const float* We12   = (const float*)d_in[16];
    const float* att12  = (const float*)d_in[17];
    const float* bias12 = (const float*)d_in[18];
    const float* bng    = (const float*)d_in[19];
    const float* bnb    = (const float*)d_in[20];
    const float* bnrm   = (const float*)d_in[21];
    const float* bnrv   = (const float*)d_in[22];

    const int N = in_sizes[0] / CIN;
    const int E = in_sizes[1] / 2;
    const int* srcp = ei;
    const int* dstp = ei + E;
    float* out = (float*)d_out;

    float *XL, *XR, *EEb, *H0, *H1, *RES;
    int *off, *cur, *eid, *cnt, *bsum;
    char* Bimg;
    cudaGetSymbolAddress((void**)&XL,  g_XL);
    cudaGetSymbolAddress((void**)&XR,  g_XR);
    cudaGetSymbolAddress((void**)&EEb, g_EE);
    cudaGetSymbolAddress((void**)&H0,  g_H0);
    cudaGetSymbolAddress((void**)&H1,  g_H1);
    cudaGetSymbolAddress((void**)&RES, g_RES);
    cudaGetSymbolAddress((void**)&off, g_off);
    cudaGetSymbolAddress((void**)&cur, g_cur);
    cudaGetSymbolAddress((void**)&eid, g_eid);
    cudaGetSymbolAddress((void**)&cnt, g_cnt);
    cudaGetSymbolAddress((void**)&bsum,g_bsum);
    cudaGetSymbolAddress((void**)&Bimg,g_Bimg);

    cudaFuncSetAttribute(tc_gemm, cudaFuncAttributeMaxDynamicSharedMemorySize, smem_size(128));

    // ---- weight image offsets (4 bytes per element: hi+lo bf16) ----
    size_t o = 0;
    const size_t OFF_RES = o; o += img_bytes(128, 64);
    const size_t OFF_WL0 = o; o += img_bytes(128, 256);
    const size_t OFF_WR0 = o; o += img_bytes(128, 256);
    const size_t OFF_WE0 = o; o += img_bytes(128, 256);
    const size_t OFF_WL1 = o; o += img_bytes(64, 256);
    const size_t OFF_WR1 = o; o += img_bytes(64, 256);
    const size_t OFF_WE1 = o; o += img_bytes(128, 256);
    const size_t OFF_WL2 = o; o += img_bytes(64, 256);
    const size_t OFF_WR2 = o; o += img_bytes(64, 256);
    const size_t OFF_WE2 = o; o += img_bytes(128, 256);

    #define IMG(off) ((__nv_bfloat16*)(Bimg + (off)))
    prep_B<<<cdiv(128 *  64, 256), 256>>>(res_W,            128,  64, IMG(OFF_RES));
    prep_B<<<cdiv(128 * 256, 256), 256>>>(Wl0,              128, 256, IMG(OFF_WL0));
    prep_B<<<cdiv(128 * 256, 256), 256>>>(Wr0,              128, 256, IMG(OFF_WR0));
    prep_B<<<cdiv(128 * 256, 256), 256>>>(We0,              128, 256, IMG(OFF_WE0));
    prep_B<<<cdiv( 64 * 256, 256), 256>>>(Wl12,              64, 256, IMG(OFF_WL1));
    prep_B<<<cdiv( 64 * 256, 256), 256>>>(Wr12,              64, 256, IMG(OFF_WR1));
    prep_B<<<cdiv(128 * 256, 256), 256>>>(We12,             128, 256, IMG(OFF_WE1));
    prep_B<<<cdiv( 64 * 256, 256), 256>>>(Wl12 + HIDC * C2,  64, 256, IMG(OFF_WL2));
    prep_B<<<cdiv( 64 * 256, 256), 256>>>(Wr12 + HIDC * C2,  64, 256, IMG(OFF_WR2));
    prep_B<<<cdiv(128 * 256, 256), 256>>>(We12 + CIN * C2,  128, 256, IMG(OFF_WE2));

    // ---- CSR by destination ----
    cudaMemsetAsync(cnt, 0, sizeof(int) * N);
    hist_kernel<<<cdiv(E, 256), 256>>>(dstp, E, cnt);
    int nb = cdiv(N, 1024);
    scan_block<<<nb, 1024>>>(cnt, N, off, bsum);
    scan_small<<<1, 32>>>(bsum, nb);
    finalize_offsets<<<cdiv(N, 256), 256>>>(N, E, bsum, off, cur);
    scatter_kernel<<<cdiv(E, 256), 256>>>(dstp, E, cur, eid);

    const int smK128 = smem_size(128);   // 139264
    const int smK64  = smem_size(64);    //  71680
    dim3 gN2(cdiv(N, 128), 2);           // node GEMMs, N=256
    dim3 gE2(cdiv(E, 128), 2);           // edge GEMMs, N=256
    dim3 gR (cdiv(N, 128), 1);           // residual,  N=64
    int aggGrid = cdiv(N * 32, 256);

    // ---- residual projection ----
    tc_gemm<<<gR, 256, smK128>>>(N, 128, 64, x, IMG(OFF_RES), res_b, RES);

    // ---- layer 0 ----
    tc_gemm<<<gN2, 256, smK128>>>(N, 128, 256, x,  IMG(OFF_WL0), bl0, XL);
    tc_gemm<<<gN2, 256, smK128>>>(N, 128, 256, x,  IMG(OFF_WR0), br0, XR);
    tc_gemm<<<gE2, 256, smK128>>>(E, 128, 256, ea, IMG(OFF_WE0), nullptr, EEb);
    gat_aggregate<<<aggGrid, 256>>>(N, XL, XR, EEb, off, eid, srcp,
                                    att0, bias0, bng, bnb, bnrm, bnrv, RES, H0, 1);

    // ---- layer 1 ----
    tc_gemm<<<gN2, 256, smK64>>>(N, 64, 256, H0, IMG(OFF_WL1), bl12, XL);
    tc_gemm<<<gN2, 256, smK64>>>(N, 64, 256, H0, IMG(OFF_WR1), br12, XR);
    tc_gemm<<<gE2, 256, smK128>>>(E, 128, 256, ea, IMG(OFF_WE1), nullptr, EEb);
    gat_aggregate<<<aggGrid, 256>>>(N, XL, XR, EEb, off, eid, srcp,
                                    att12, bias12, bng + HIDC, bnb + HIDC,
                                    bnrm + HIDC, bnrv + HIDC, H0, H1, 1);

    // ---- layer 2 (final conv) ----
    tc_gemm<<<gN2, 256, smK64>>>(N, 64, 256, H1, IMG(OFF_WL2), bl12 + C2, XL);
    tc_gemm<<<gN2, 256, smK64>>>(N, 64, 256, H1, IMG(OFF_WR2), br12 + C2, XR);
    tc_gemm<<<gE2, 256, smK128>>>(E, 128, 256, ea, IMG(OFF_WE2), nullptr, EEb);
    gat_aggregate<<<aggGrid, 256>>>(N, XL, XR, EEb, off, eid, srcp,
                                    att12 + C2, bias12 + HIDC,
                                    nullptr, nullptr, nullptr, nullptr, nullptr, out, 0);

    // ---- second output: edge_attr passthrough ----
    copy_f4<<<4096, 256>>>((const float4*)ea, (float4*)(out + (size_t)N * HIDC),
                           E * CIN / 4);
    #undef IMG
}